// round 1
// baseline (speedup 1.0000x reference)
#include <cuda_runtime.h>

// Problem constants
static constexpr int N_MC = 32;
static constexpr int M    = 8192;
static constexpr int D    = 16;

#define TWOPI_F  6.2831853071795864769f     // rounds to float32(2*pi) = 6.2831855f
#define INV2PI_F 0.15915494309189535f
#define NEG_HALF_LOG_2PI -0.9189385332046727f

// Scratch: per-(m,d) precomputed (scale, 1/scale), per-m constant C_m = sum_d log_norm
__device__ float2 g_sinv[M * D];
__device__ float  g_C[M];

// Pass 1: 131072 threads. Compute softplus EXACTLY as jax.nn.softplus =
// max(x,0) + log1p(exp(-|x|)) using precise libdevice expf/log1pf so that
// scale (and hence x = eps*scale and the mod boundary) bit-matches XLA.
__global__ void relie_prep(const float* __restrict__ gamma_raw) {
    int tid = blockIdx.x * blockDim.x + threadIdx.x;   // 0 .. M*D-1
    float raw = gamma_raw[tid];
    float s   = fmaxf(raw, 0.0f) + log1pf(expf(-fabsf(raw)));
    float inv = 1.0f / s;
    float ln  = NEG_HALF_LOG_2PI - logf(s);
    g_sinv[tid] = make_float2(s, inv);
    // Sum log_norm over the 16 dims of each row (lanes d = tid&15 are
    // contiguous within the warp, xor masks 1,2,4,8 stay inside the group).
    ln += __shfl_xor_sync(0xffffffffu, ln, 1);
    ln += __shfl_xor_sync(0xffffffffu, ln, 2);
    ln += __shfl_xor_sync(0xffffffffu, ln, 4);
    ln += __shfl_xor_sync(0xffffffffu, ln, 8);
    if ((tid & 15) == 0) g_C[tid >> 4] = ln;
}

// Pass 2: N*M*4 threads; each thread owns 4 consecutive dims of one (n,m) pair.
// Fully coalesced float4 traffic on eps/g; (s,1/s) and mu hit L2 (reused 32x).
__global__ void __launch_bounds__(256) relie_main(
    const float4* __restrict__ eps4,   // N*M*4 float4
    const float4* __restrict__ mu4,    // M*4 float4
    float4*       __restrict__ g4,     // N*M*4 float4
    float*        __restrict__ lq)     // N*M floats
{
    int gid = blockIdx.x * blockDim.x + threadIdx.x;   // 0 .. N*M*4-1
    int nm  = gid >> 2;
    int dq  = gid & 3;
    int m   = nm & (M - 1);

    float4 e  = eps4[gid];
    float4 mu = mu4[(m << 2) + dq];
    const float4* sv = reinterpret_cast<const float4*>(g_sinv);
    float4 s01 = sv[(m << 3) + (dq << 1)];       // (s0,i0,s1,i1)
    float4 s23 = sv[(m << 3) + (dq << 1) + 1];   // (s2,i2,s3,i3)

    float ev[4] = { e.x, e.y, e.z, e.w };
    float mv[4] = { mu.x, mu.y, mu.z, mu.w };
    float ss[4] = { s01.x, s01.z, s23.x, s23.z };
    float iv[4] = { s01.y, s01.w, s23.y, s23.w };
    float gv[4];

    float lacc = 0.0f;
    #pragma unroll
    for (int j = 0; j < 4; j++) {
        float x = ev[j] * ss[j];

        // ---- g = mod(x + mu, 2pi): replicate jnp.remainder exactly ----
        // trunc_mod = fmodf (exact per IEEE, matches XLA's rem lowering);
        // add 2pi when trunc_mod < 0 (divisor positive).  This keeps the
        // wrap boundary bit-identical to the reference -> no 2pi-sized
        // per-element errors.
        float v = x + mv[j];
        float t = fmodf(v, TWOPI_F);
        if (t < 0.0f) t += TWOPI_F;
        gv[j] = t;

        // ---- lq: center x into [-pi, pi], then 5-term lattice sum ----
        // After centering, the nearest omitted shift is >= 5*pi away:
        // exp(-0.5*(5pi/s_max)^2) ~ exp(-34) == 0 in f32.  All retained
        // terms lie inside the reference's k in [-5,5] window.
        float r = x - TWOPI_F * rintf(x * INV2PI_F);
        float u  = r * iv[j];
        float a  = TWOPI_F * iv[j];
        float u1 = u - a;
        float u2 = u - 2.0f * a;
        float u3 = u + a;
        float u4 = u + 2.0f * a;
        float acc = __expf(-0.5f * u  * u )
                  + __expf(-0.5f * u1 * u1)
                  + __expf(-0.5f * u2 * u2)
                  + __expf(-0.5f * u3 * u3)
                  + __expf(-0.5f * u4 * u4);
        lacc += __logf(acc);
    }

    g4[gid] = make_float4(gv[0], gv[1], gv[2], gv[3]);

    // Reduce the partial D-sum across the 4 lanes owning this (n,m)
    lacc += __shfl_xor_sync(0xffffffffu, lacc, 1);
    lacc += __shfl_xor_sync(0xffffffffu, lacc, 2);
    if (dq == 0) lq[nm] = lacc + g_C[m];
}

extern "C" void kernel_launch(void* const* d_in, const int* in_sizes, int n_in,
                              void* d_out, int out_size) {
    const float* eps       = (const float*)d_in[0];  // (32, 8192, 16)
    const float* gamma_raw = (const float*)d_in[1];  // (8192, 16)
    const float* mu        = (const float*)d_in[2];  // (8192, 16)

    float* g_out  = (float*)d_out;                   // first N*M*D floats
    float* lq_out = (float*)d_out + (size_t)N_MC * M * D;  // next N*M floats

    // Pass 1: per-(m,d) precompute.  M*D = 131072 threads.
    relie_prep<<<(M * D) / 256, 256>>>(gamma_raw);

    // Pass 2: main fused kernel.  N*M*4 = 1048576 threads.
    relie_main<<<(N_MC * M * 4) / 256, 256>>>(
        (const float4*)eps, (const float4*)mu, (float4*)g_out, lq_out);
}

// round 2
// speedup vs baseline: 1.4363x; 1.4363x over previous
#include <cuda_runtime.h>

// Problem constants
static constexpr int N_MC = 32;
static constexpr int M    = 8192;
static constexpr int D    = 16;

#define TWOPI_F   6.2831853071795864769f   // rounds to float32(2*pi)
#define INV2PI_F  0.15915494309189535f
#define NEG_HALF_LOG_2PI -0.9189385332046727f
#define C_EX2     (-0.72134752044448170368f)  // -0.5 * log2(e)
#define LN2_F     0.69314718055994530942f

// Scratch: per-(m,d) precomputed (scale, 1/scale), per-m constant C_m = sum_d log_norm
__device__ float2 g_sinv[M * D];
__device__ float  g_C[M];

__device__ __forceinline__ float ex2f(float x) {
    float y; asm("ex2.approx.f32 %0, %1;" : "=f"(y) : "f"(x)); return y;
}
__device__ __forceinline__ float lg2f(float x) {
    float y; asm("lg2.approx.f32 %0, %1;" : "=f"(y) : "f"(x)); return y;
}

// Pass 1: 131072 threads. scale = softplus(raw) computed EXACTLY as
// jax.nn.softplus = max(x,0) + log1p(exp(-|x|)) with precise libdevice
// expf/log1pf so x = eps*scale (and the mod boundary) bit-matches XLA.
// The log term only feeds lq (loose tolerance) -> fast lg2.
__global__ void relie_prep(const float* __restrict__ gamma_raw) {
    int tid = blockIdx.x * blockDim.x + threadIdx.x;   // 0 .. M*D-1
    float raw = gamma_raw[tid];
    float s   = fmaxf(raw, 0.0f) + log1pf(expf(-fabsf(raw)));
    float inv = 1.0f / s;
    float ln  = NEG_HALF_LOG_2PI - LN2_F * lg2f(s);
    g_sinv[tid] = make_float2(s, inv);
    ln += __shfl_xor_sync(0xffffffffu, ln, 1);
    ln += __shfl_xor_sync(0xffffffffu, ln, 2);
    ln += __shfl_xor_sync(0xffffffffu, ln, 4);
    ln += __shfl_xor_sync(0xffffffffu, ln, 8);
    if ((tid & 15) == 0) g_C[tid >> 4] = ln;
}

// Pass 2: N*M*4 threads; each thread owns 4 consecutive dims of one (n,m).
__global__ void __launch_bounds__(256) relie_main(
    const float4* __restrict__ eps4,   // N*M*4 float4
    const float4* __restrict__ mu4,    // M*4 float4
    float4*       __restrict__ g4,     // N*M*4 float4
    float*        __restrict__ lq)     // N*M floats
{
    int gid = blockIdx.x * blockDim.x + threadIdx.x;   // 0 .. N*M*4-1
    int nm  = gid >> 2;
    int dq  = gid & 3;
    int m   = nm & (M - 1);

    float4 e  = eps4[gid];
    float4 mu = mu4[(m << 2) + dq];
    const float4* sv = reinterpret_cast<const float4*>(g_sinv);
    float4 s01 = sv[(m << 3) + (dq << 1)];       // (s0,i0,s1,i1)
    float4 s23 = sv[(m << 3) + (dq << 1) + 1];   // (s2,i2,s3,i3)

    float ev[4] = { e.x, e.y, e.z, e.w };
    float mv[4] = { mu.x, mu.y, mu.z, mu.w };
    float ss[4] = { s01.x, s01.z, s23.x, s23.z };
    float iv[4] = { s01.y, s01.w, s23.y, s23.w };
    float gv[4];

    float lacc2 = 0.0f;   // logsumexp accumulated in log2 domain
    #pragma unroll
    for (int j = 0; j < 4; j++) {
        float x = ev[j] * ss[j];

        // ---- g = mod(x + mu, 2pi), bit-identical to exact fmodf + fixup ----
        // |v| < 17 so the quotient is a small integer.  With q = rint(v/2pi):
        //  * frac<1/2: fma's real result IS the (representable) remainder -> exact.
        //  * frac>1/2: fma computes t_ref - 2pi, exact by Sterbenz; the fixup
        //    add's true result t_ref is representable -> returned exactly.
        // Negative v reduces to the same cases / the identical fixup rounding
        // the reference performs.  No 2pi-flip risk.
        float v = x + mv[j];
        float q = rintf(v * INV2PI_F);
        float t = fmaf(q, -TWOPI_F, v);
        if (t < 0.0f) t += TWOPI_F;
        gv[j] = t;

        // ---- lq: center x into [-pi,pi]; 3-term lattice sum suffices ----
        // Dropped k=+-2 terms are >= 3pi/s out: worst relative weight
        // exp(-4*pi^2/s^2)/2 <= 1.7e-5 for s <= 1.96 -> |d lq| <~ 1e-4 abs.
        float qr = rintf(x * INV2PI_F);
        float r  = fmaf(qr, -TWOPI_F, x);
        float u  = r * iv[j];
        float a  = TWOPI_F * iv[j];
        float u1 = u - a;
        float u3 = u + a;
        float e0 = ex2f(u  * u  * C_EX2);
        float e1 = ex2f(u1 * u1 * C_EX2);
        float e3 = ex2f(u3 * u3 * C_EX2);
        lacc2 += lg2f((e1 + e3) + e0);
    }

    g4[gid] = make_float4(gv[0], gv[1], gv[2], gv[3]);

    // Reduce the partial D-sum across the 4 lanes owning this (n,m)
    lacc2 += __shfl_xor_sync(0xffffffffu, lacc2, 1);
    lacc2 += __shfl_xor_sync(0xffffffffu, lacc2, 2);
    if (dq == 0) lq[nm] = fmaf(lacc2, LN2_F, g_C[m]);
}

extern "C" void kernel_launch(void* const* d_in, const int* in_sizes, int n_in,
                              void* d_out, int out_size) {
    const float* eps       = (const float*)d_in[0];  // (32, 8192, 16)
    const float* gamma_raw = (const float*)d_in[1];  // (8192, 16)
    const float* mu        = (const float*)d_in[2];  // (8192, 16)

    float* g_out  = (float*)d_out;                          // N*M*D floats
    float* lq_out = (float*)d_out + (size_t)N_MC * M * D;   // N*M floats

    relie_prep<<<(M * D) / 256, 256>>>(gamma_raw);
    relie_main<<<(N_MC * M * 4) / 256, 256>>>(
        (const float4*)eps, (const float4*)mu, (float4*)g_out, lq_out);
}